// round 1
// baseline (speedup 1.0000x reference)
#include <cuda_runtime.h>
#include <math.h>

#define F_DIM 128
#define NRBF  20
#define MAXN  10000
#define MAXE  320000
#define NLAYERS 3

// ---------------- device scratch (allocation-free) ----------------
__device__ float g_dir  [MAXE * 3];
__device__ float g_phif [MAXE * NRBF];   // phi * fcut
__device__ float g_fcut [MAXE];
__device__ int   g_rowptr[MAXN + 1];
__device__ float g_x    [MAXN * 384];    // interaction x, reused for mixing x2
__device__ float g_h    [MAXN * 128];
__device__ float g_muA  [MAXN * 384];    // ping-pong partner of d_out mu region
__device__ float g_mumix[MAXN * 768];    // [N,3,256]
__device__ float g_ctx  [MAXN * 256];
__device__ float g_s    [MAXN * 128];

// ---------------- precompute per-edge geometry + RBF ----------------
__global__ void pre_kernel(const float* __restrict__ r_ij, int E) {
    int e = blockIdx.x * blockDim.x + threadIdx.x;
    if (e >= E) return;
    float x = r_ij[e * 3 + 0];
    float y = r_ij[e * 3 + 1];
    float z = r_ij[e * 3 + 2];
    float d = sqrtf(x * x + y * y + z * z);
    float inv = 1.0f / d;
    g_dir[e * 3 + 0] = x * inv;
    g_dir[e * 3 + 1] = y * inv;
    g_dir[e * 3 + 2] = z * inv;
    float fc = (d < 5.0f) ? 0.5f * (cosf(d * 0.62831853071795864769f) + 1.0f) : 0.0f;
    g_fcut[e] = fc;
    const float delta = 5.0f / 19.0f;
    const float coeff = -0.5f / (delta * delta);
#pragma unroll
    for (int r = 0; r < NRBF; r++) {
        float diff = d - delta * (float)r;
        g_phif[e * NRBF + r] = expf(coeff * diff * diff) * fc;
    }
}

// ---------------- segment boundaries (idx_i sorted) ----------------
__global__ void rowptr_kernel(const int* __restrict__ idx_i, int E, int N) {
    int i = blockIdx.x * blockDim.x + threadIdx.x;
    if (i > N) return;
    int lo = 0, hi = E;
    while (lo < hi) {
        int mid = (lo + hi) >> 1;
        if (idx_i[mid] < i) lo = mid + 1; else hi = mid;
    }
    g_rowptr[i] = lo;
}

// ---------------- init q = embedding[an], muA = 0 ----------------
__global__ void init_kernel(const int* __restrict__ an, const float* __restrict__ emb,
                            float* __restrict__ q, int N) {
    int t = blockIdx.x * blockDim.x + threadIdx.x;
    if (t < N * 384) g_muA[t] = 0.0f;
    if (t < N * 128) {
        int n = t >> 7, c = t & 127;
        q[t] = emb[an[n] * 128 + c];
    }
}

// ---------------- tiled fp32 GEMM: C = act(A[M,K] @ W[K,N] + bias) ----------------
// BM=128 BN=128 BK=16, 256 threads, 8x8 per thread.  N multiple of 128, K multiple of 16.
template <int ACT>   // 0 = none, 1 = silu
__global__ void gemm_kernel(const float* __restrict__ A, const float* __restrict__ W,
                            const float* __restrict__ bias, float* __restrict__ C,
                            int M, int N, int K) {
    __shared__ float As[16][128];
    __shared__ float Bs[16][128];
    int tid  = threadIdx.x;
    int row0 = blockIdx.y * 128;
    int col0 = blockIdx.x * 128;
    int tr = (tid / 16) * 8;
    int tc = (tid % 16) * 8;
    float acc[8][8];
#pragma unroll
    for (int i = 0; i < 8; i++)
#pragma unroll
        for (int j = 0; j < 8; j++) acc[i][j] = 0.0f;

    for (int k0 = 0; k0 < K; k0 += 16) {
        // A tile 128x16 = 512 float4
#pragma unroll
        for (int i = 0; i < 2; i++) {
            int s = tid + i * 256;
            int r = s >> 2;
            int kk = (s & 3) * 4;
            float4 v;
            if (row0 + r < M) v = *(const float4*)&A[(size_t)(row0 + r) * K + k0 + kk];
            else              v = make_float4(0.f, 0.f, 0.f, 0.f);
            As[kk + 0][r] = v.x; As[kk + 1][r] = v.y;
            As[kk + 2][r] = v.z; As[kk + 3][r] = v.w;
        }
        // W tile 16x128 = 512 float4
#pragma unroll
        for (int i = 0; i < 2; i++) {
            int s = tid + i * 256;
            int r = s >> 5;
            int c = (s & 31) * 4;
            *(float4*)&Bs[r][c] = *(const float4*)&W[(size_t)(k0 + r) * N + col0 + c];
        }
        __syncthreads();
#pragma unroll
        for (int kk = 0; kk < 16; kk++) {
            float a[8], b[8];
            *(float4*)&a[0] = *(const float4*)&As[kk][tr];
            *(float4*)&a[4] = *(const float4*)&As[kk][tr + 4];
            *(float4*)&b[0] = *(const float4*)&Bs[kk][tc];
            *(float4*)&b[4] = *(const float4*)&Bs[kk][tc + 4];
#pragma unroll
            for (int i = 0; i < 8; i++)
#pragma unroll
                for (int j = 0; j < 8; j++)
                    acc[i][j] = fmaf(a[i], b[j], acc[i][j]);
        }
        __syncthreads();
    }
#pragma unroll
    for (int i = 0; i < 8; i++) {
        int r = row0 + tr + i;
        if (r >= M) continue;
#pragma unroll
        for (int j = 0; j < 8; j += 4) {
            float4 v;
            float* pv = &v.x;
#pragma unroll
            for (int t = 0; t < 4; t++) {
                float val = acc[i][j + t];
                if (bias) val += bias[col0 + tc + j + t];
                if (ACT == 1) val = val / (1.0f + expf(-val));
                pv[t] = val;
            }
            *(float4*)&C[(size_t)r * N + col0 + tc + j] = v;
        }
    }
}

// ---------------- edge message + segment-sum kernel ----------------
// One block (128 threads) per node (grid-stride). Thread c owns feature c.
// Filter weights for this layer's 3 chunks held in registers (loop-invariant).
__global__ void edge_kernel(const float* __restrict__ x,
                            float* __restrict__ q,
                            const float* __restrict__ mu_in,
                            float* __restrict__ mu_out,
                            const int* __restrict__ idx_j,
                            const float* __restrict__ filt_W,
                            const float* __restrict__ filt_b,
                            int layer, int N) {
    int c = threadIdx.x;   // 0..127
    int layOff = layer * 384;
    float WQc[NRBF], WRc[NRBF], WMc[NRBF];
#pragma unroll
    for (int r = 0; r < NRBF; r++) {
        const float* fw = &filt_W[r * (NLAYERS * 384) + layOff];
        WQc[r] = fw[c];
        WRc[r] = fw[128 + c];
        WMc[r] = fw[256 + c];
    }
    float FBq = filt_b[layOff + c];
    float FBr = filt_b[layOff + 128 + c];
    float FBm = filt_b[layOff + 256 + c];

    for (int node = blockIdx.x; node < N; node += gridDim.x) {
        int e0 = g_rowptr[node], e1 = g_rowptr[node + 1];
        float accq = 0.f, am0 = 0.f, am1 = 0.f, am2 = 0.f;
        for (int e = e0; e < e1; e++) {
            int j = idx_j[e];
            const float* pp = &g_phif[(size_t)e * NRBF];
            float fc = g_fcut[e];
            float Wq = fc * FBq, Wr = fc * FBr, Wm = fc * FBm;
#pragma unroll
            for (int r = 0; r < NRBF; r++) {
                float p = pp[r];
                Wq = fmaf(p, WQc[r], Wq);
                Wr = fmaf(p, WRc[r], Wr);
                Wm = fmaf(p, WMc[r], Wm);
            }
            const float* xr = &x[(size_t)j * 384];
            float xq = xr[c], xR = xr[128 + c], xM = xr[256 + c];
            float d0 = g_dir[e * 3 + 0], d1 = g_dir[e * 3 + 1], d2 = g_dir[e * 3 + 2];
            accq = fmaf(Wq, xq, accq);
            float t   = Wr * xR;
            float wmx = Wm * xM;
            const float* mj = &mu_in[(size_t)j * 384];
            am0 = fmaf(t, d0, fmaf(wmx, mj[c],       am0));
            am1 = fmaf(t, d1, fmaf(wmx, mj[128 + c], am1));
            am2 = fmaf(t, d2, fmaf(wmx, mj[256 + c], am2));
        }
        q[(size_t)node * 128 + c] += accq;
        size_t mb = (size_t)node * 384;
        mu_out[mb + c]       = mu_in[mb + c]       + am0;
        mu_out[mb + 128 + c] = mu_in[mb + 128 + c] + am1;
        mu_out[mb + 256 + c] = mu_in[mb + 256 + c] + am2;
    }
}

// ---------------- mixing stage 1: norms, dot, build ctx ----------------
__global__ void mix1_kernel(const float* __restrict__ q, int N) {
    int t = blockIdx.x * blockDim.x + threadIdx.x;
    if (t >= N * 128) return;
    int n = t >> 7, c = t & 127;
    const float* mm = &g_mumix[(size_t)n * 768];
    float v0 = mm[c],        v1 = mm[256 + c], v2 = mm[512 + c];
    float w0 = mm[128 + c],  w1 = mm[384 + c], w2 = mm[640 + c];
    float vn = sqrtf(v0 * v0 + v1 * v1 + v2 * v2 + 1e-8f);
    g_ctx[(size_t)n * 256 + c]       = q[t];
    g_ctx[(size_t)n * 256 + 128 + c] = vn;
    g_s[t] = v0 * w0 + v1 * w1 + v2 * w2;
}

// ---------------- mixing stage 2: final per-node update ----------------
__global__ void epi2_kernel(float* __restrict__ q, float* __restrict__ mu, int N) {
    int t = blockIdx.x * blockDim.x + threadIdx.x;
    if (t >= N * 128) return;
    int n = t >> 7, c = t & 127;
    const float* xr = &g_x[(size_t)n * 384];
    float dq   = xr[c];
    float dmu  = xr[128 + c];
    float dqmu = xr[256 + c];
    q[t] += dq + dqmu * g_s[t];
    const float* mm = &g_mumix[(size_t)n * 768];
    size_t mb = (size_t)n * 384;
    mu[mb + c]       += dmu * mm[128 + c];
    mu[mb + 128 + c] += dmu * mm[384 + c];
    mu[mb + 256 + c] += dmu * mm[640 + c];
}

// ---------------- host launch ----------------
extern "C" void kernel_launch(void* const* d_in, const int* in_sizes, int n_in,
                              void* d_out, int out_size) {
    const int*   an     = (const int*)  d_in[0];
    const float* r_ij   = (const float*)d_in[1];
    const int*   idx_i  = (const int*)  d_in[2];
    const int*   idx_j  = (const int*)  d_in[3];
    const float* emb    = (const float*)d_in[4];
    const float* filt_W = (const float*)d_in[5];
    const float* filt_b = (const float*)d_in[6];
    const float* int_W1 = (const float*)d_in[7];
    const float* int_b1 = (const float*)d_in[8];
    const float* int_W2 = (const float*)d_in[9];
    const float* int_b2 = (const float*)d_in[10];
    const float* mix_W1 = (const float*)d_in[11];
    const float* mix_b1 = (const float*)d_in[12];
    const float* mix_W2 = (const float*)d_in[13];
    const float* mix_b2 = (const float*)d_in[14];
    const float* mux_W  = (const float*)d_in[15];

    int N = in_sizes[0];
    int E = in_sizes[3];

    float* q      = (float*)d_out;          // [N,128]
    float* mu_out = q + (size_t)N * 128;    // [N,3,128]

    void* pA;
    cudaGetSymbolAddress(&pA, g_muA);
    float* muA = (float*)pA;
    void* pH; cudaGetSymbolAddress(&pH, g_h);    float* h    = (float*)pH;
    void* pX; cudaGetSymbolAddress(&pX, g_x);    float* xbuf = (float*)pX;
    void* pM; cudaGetSymbolAddress(&pM, g_mumix);float* mumix= (float*)pM;
    void* pC; cudaGetSymbolAddress(&pC, g_ctx);  float* ctx  = (float*)pC;

    // precompute
    pre_kernel   <<<(E + 255) / 256, 256>>>(r_ij, E);
    rowptr_kernel<<<(N + 256) / 256, 256>>>(idx_i, E, N);
    init_kernel  <<<((size_t)N * 384 + 255) / 256, 256>>>(an, emb, q, N);

    const int EDGE_GRID = 1480;   // grid-stride over nodes

    for (int l = 0; l < NLAYERS; l++) {
        float* mu_in  = (l & 1) ? mu_out : muA;
        float* mu_o   = (l & 1) ? muA    : mu_out;

        // interaction: h = silu(q W1 + b1); x = h W2 + b2
        {
            dim3 g(128 / 128, (N + 127) / 128);
            gemm_kernel<1><<<g, 256>>>(q, int_W1 + (size_t)l * 128 * 128,
                                       int_b1 + l * 128, h, N, 128, 128);
        }
        {
            dim3 g(384 / 128, (N + 127) / 128);
            gemm_kernel<0><<<g, 256>>>(h, int_W2 + (size_t)l * 128 * 384,
                                       int_b2 + l * 384, xbuf, N, 384, 128);
        }
        // edge messages + segment sum
        edge_kernel<<<EDGE_GRID, 128>>>(xbuf, q, mu_in, mu_o, idx_j,
                                        filt_W, filt_b, l, N);
        // mixing: mumix = mu @ mux_W  (no bias), A viewed as [3N,128]
        {
            dim3 g(256 / 128, (3 * N + 127) / 128);
            gemm_kernel<0><<<g, 256>>>(mu_o, mux_W + (size_t)l * 128 * 256,
                                       nullptr, mumix, 3 * N, 256, 128);
        }
        mix1_kernel<<<((size_t)N * 128 + 255) / 256, 256>>>(q, N);
        // h = silu(ctx mix_W1 + b1)
        {
            dim3 g(128 / 128, (N + 127) / 128);
            gemm_kernel<1><<<g, 256>>>(ctx, mix_W1 + (size_t)l * 256 * 128,
                                       mix_b1 + l * 128, h, N, 128, 256);
        }
        // x2 = h mix_W2 + b2  (into xbuf)
        {
            dim3 g(384 / 128, (N + 127) / 128);
            gemm_kernel<0><<<g, 256>>>(h, mix_W2 + (size_t)l * 128 * 384,
                                       mix_b2 + l * 384, xbuf, N, 384, 128);
        }
        epi2_kernel<<<((size_t)N * 128 + 255) / 256, 256>>>(q, mu_o, N);
    }
    // layer parity: l=0 in=muA out=d_out, l=1 in=d_out out=muA, l=2 in=muA out=d_out.
    // Final q and mu land in d_out. (q lives in d_out throughout.)
}

// round 2
// speedup vs baseline: 1.0671x; 1.0671x over previous
#include <cuda_runtime.h>
#include <math.h>

#define F_DIM 128
#define NRBF  20
#define MAXN  10000
#define MAXE  320000
#define NLAYERS 3

// ---------------- device scratch (allocation-free) ----------------
__device__ float g_dir  [MAXE * 3];
__device__ float g_phif [MAXE * NRBF];   // phi * fcut
__device__ float g_fcut [MAXE];
__device__ int   g_rowptr[MAXN + 1];
__device__ float g_x    [MAXN * 384];    // interaction x, reused for mixing x2
__device__ float g_h    [MAXN * 128];
__device__ float g_muA  [MAXN * 384];    // ping-pong partner of d_out mu region
__device__ float g_mumix[MAXN * 768];    // [N,3,256]
__device__ float g_ctx  [MAXN * 256];
__device__ float g_s    [MAXN * 128];

// ---------------- precompute per-edge geometry + RBF ----------------
__global__ void pre_kernel(const float* __restrict__ r_ij, int E) {
    int e = blockIdx.x * blockDim.x + threadIdx.x;
    if (e >= E) return;
    float x = r_ij[e * 3 + 0];
    float y = r_ij[e * 3 + 1];
    float z = r_ij[e * 3 + 2];
    float d = sqrtf(x * x + y * y + z * z);
    float inv = 1.0f / d;
    g_dir[e * 3 + 0] = x * inv;
    g_dir[e * 3 + 1] = y * inv;
    g_dir[e * 3 + 2] = z * inv;
    float fc = (d < 5.0f) ? 0.5f * (cosf(d * 0.62831853071795864769f) + 1.0f) : 0.0f;
    g_fcut[e] = fc;
    const float delta = 5.0f / 19.0f;
    const float coeff = -0.5f / (delta * delta);
#pragma unroll
    for (int r = 0; r < NRBF; r++) {
        float diff = d - delta * (float)r;
        g_phif[e * NRBF + r] = expf(coeff * diff * diff) * fc;
    }
}

// ---------------- segment boundaries (idx_i sorted) ----------------
__global__ void rowptr_kernel(const int* __restrict__ idx_i, int E, int N) {
    int i = blockIdx.x * blockDim.x + threadIdx.x;
    if (i > N) return;
    int lo = 0, hi = E;
    while (lo < hi) {
        int mid = (lo + hi) >> 1;
        if (idx_i[mid] < i) lo = mid + 1; else hi = mid;
    }
    g_rowptr[i] = lo;
}

// ---------------- init q = embedding[an], muA = 0 ----------------
__global__ void init_kernel(const int* __restrict__ an, const float* __restrict__ emb,
                            float* __restrict__ q, int N) {
    int t = blockIdx.x * blockDim.x + threadIdx.x;
    if (t < N * 384) g_muA[t] = 0.0f;
    if (t < N * 128) {
        int n = t >> 7, c = t & 127;
        q[t] = emb[an[n] * 128 + c];
    }
}

// ---------------- double-buffered fp32 GEMM: C = act(A[M,K] @ W[K,N] + bias) --
// BM=BN=64, BK=16, 256 threads, 4x4 per thread. N % 64 == 0, K % 16 == 0.
template <int ACT>   // 0 = none, 1 = silu
__global__ void __launch_bounds__(256)
gemm64(const float* __restrict__ A, const float* __restrict__ W,
       const float* __restrict__ bias, float* __restrict__ C,
       int M, int N, int K) {
    __shared__ float As[2][16][68];   // [buf][k][m], pad 68 to break store conflicts
    __shared__ float Bs[2][16][68];   // [buf][k][n]
    const int tid  = threadIdx.x;
    const int row0 = blockIdx.y * 64;
    const int col0 = blockIdx.x * 64;
    const int tx = tid & 15, ty = tid >> 4;
    const int ar = tid >> 2;            // 0..63 (A row within tile)
    const int ak = (tid & 3) << 2;      // 0,4,8,12 (k offset)
    const int br = tid >> 4;            // 0..15 (B k-row)
    const int bc = (tid & 15) << 2;     // 0..60 (B col offset)

    const float* Aptr = A + (size_t)(row0 + ar) * K + ak;
    const bool aval = (row0 + ar) < M;

    float4 aReg = aval ? *(const float4*)Aptr : make_float4(0.f, 0.f, 0.f, 0.f);
    float4 bReg = *(const float4*)&W[(size_t)br * N + col0 + bc];
    As[0][ak + 0][ar] = aReg.x; As[0][ak + 1][ar] = aReg.y;
    As[0][ak + 2][ar] = aReg.z; As[0][ak + 3][ar] = aReg.w;
    *(float4*)&Bs[0][br][bc] = bReg;
    __syncthreads();

    float acc[4][4];
#pragma unroll
    for (int i = 0; i < 4; i++)
#pragma unroll
        for (int j = 0; j < 4; j++) acc[i][j] = 0.0f;

    int buf = 0;
    for (int k0 = 16; k0 < K; k0 += 16) {
        // prefetch next tile into registers
        aReg = aval ? *(const float4*)(Aptr + k0) : make_float4(0.f, 0.f, 0.f, 0.f);
        bReg = *(const float4*)&W[(size_t)(k0 + br) * N + col0 + bc];
        // compute current buffer
#pragma unroll
        for (int kk = 0; kk < 16; kk++) {
            float4 a = *(const float4*)&As[buf][kk][ty << 2];
            float4 b = *(const float4*)&Bs[buf][kk][tx << 2];
            acc[0][0] = fmaf(a.x, b.x, acc[0][0]); acc[0][1] = fmaf(a.x, b.y, acc[0][1]);
            acc[0][2] = fmaf(a.x, b.z, acc[0][2]); acc[0][3] = fmaf(a.x, b.w, acc[0][3]);
            acc[1][0] = fmaf(a.y, b.x, acc[1][0]); acc[1][1] = fmaf(a.y, b.y, acc[1][1]);
            acc[1][2] = fmaf(a.y, b.z, acc[1][2]); acc[1][3] = fmaf(a.y, b.w, acc[1][3]);
            acc[2][0] = fmaf(a.z, b.x, acc[2][0]); acc[2][1] = fmaf(a.z, b.y, acc[2][1]);
            acc[2][2] = fmaf(a.z, b.z, acc[2][2]); acc[2][3] = fmaf(a.z, b.w, acc[2][3]);
            acc[3][0] = fmaf(a.w, b.x, acc[3][0]); acc[3][1] = fmaf(a.w, b.y, acc[3][1]);
            acc[3][2] = fmaf(a.w, b.z, acc[3][2]); acc[3][3] = fmaf(a.w, b.w, acc[3][3]);
        }
        // store prefetched tile into the other buffer
        buf ^= 1;
        As[buf][ak + 0][ar] = aReg.x; As[buf][ak + 1][ar] = aReg.y;
        As[buf][ak + 2][ar] = aReg.z; As[buf][ak + 3][ar] = aReg.w;
        *(float4*)&Bs[buf][br][bc] = bReg;
        __syncthreads();
    }
    // final tile
#pragma unroll
    for (int kk = 0; kk < 16; kk++) {
        float4 a = *(const float4*)&As[buf][kk][ty << 2];
        float4 b = *(const float4*)&Bs[buf][kk][tx << 2];
        acc[0][0] = fmaf(a.x, b.x, acc[0][0]); acc[0][1] = fmaf(a.x, b.y, acc[0][1]);
        acc[0][2] = fmaf(a.x, b.z, acc[0][2]); acc[0][3] = fmaf(a.x, b.w, acc[0][3]);
        acc[1][0] = fmaf(a.y, b.x, acc[1][0]); acc[1][1] = fmaf(a.y, b.y, acc[1][1]);
        acc[1][2] = fmaf(a.y, b.z, acc[1][2]); acc[1][3] = fmaf(a.y, b.w, acc[1][3]);
        acc[2][0] = fmaf(a.z, b.x, acc[2][0]); acc[2][1] = fmaf(a.z, b.y, acc[2][1]);
        acc[2][2] = fmaf(a.z, b.z, acc[2][2]); acc[2][3] = fmaf(a.z, b.w, acc[2][3]);
        acc[3][0] = fmaf(a.w, b.x, acc[3][0]); acc[3][1] = fmaf(a.w, b.y, acc[3][1]);
        acc[3][2] = fmaf(a.w, b.z, acc[3][2]); acc[3][3] = fmaf(a.w, b.w, acc[3][3]);
    }

    // epilogue
#pragma unroll
    for (int i = 0; i < 4; i++) {
        int r = row0 + (ty << 2) + i;
        if (r >= M) continue;
        float4 v;
        float* pv = &v.x;
#pragma unroll
        for (int j = 0; j < 4; j++) {
            float val = acc[i][j];
            if (bias) val += bias[col0 + (tx << 2) + j];
            if (ACT == 1) val = val / (1.0f + expf(-val));
            pv[j] = val;
        }
        *(float4*)&C[(size_t)r * N + col0 + (tx << 2)] = v;
    }
}

// ---------------- edge message + segment-sum kernel ----------------
// One block (128 threads) per node. Thread c owns feature c.
// Filter weights for this layer's 3 chunks held in registers (loop-invariant).
__global__ void __launch_bounds__(128)
edge_kernel(const float* __restrict__ x,
            float* __restrict__ q,
            const float* __restrict__ mu_in,
            float* __restrict__ mu_out,
            const int* __restrict__ idx_j,
            const float* __restrict__ filt_W,
            const float* __restrict__ filt_b,
            int layer, int N) {
    int c = threadIdx.x;   // 0..127
    int layOff = layer * 384;
    float WQc[NRBF], WRc[NRBF], WMc[NRBF];
#pragma unroll
    for (int r = 0; r < NRBF; r++) {
        const float* fw = &filt_W[r * (NLAYERS * 384) + layOff];
        WQc[r] = fw[c];
        WRc[r] = fw[128 + c];
        WMc[r] = fw[256 + c];
    }
    float FBq = filt_b[layOff + c];
    float FBr = filt_b[layOff + 128 + c];
    float FBm = filt_b[layOff + 256 + c];

    int node = blockIdx.x;
    if (node >= N) return;
    int e0 = g_rowptr[node], e1 = g_rowptr[node + 1];
    float accq = 0.f, am0 = 0.f, am1 = 0.f, am2 = 0.f;
    for (int e = e0; e < e1; e++) {
        int j = idx_j[e];
        // phif row: 20 floats, 16B-aligned -> 5 vector loads
        float p[NRBF];
        const float4* pp4 = (const float4*)&g_phif[(size_t)e * NRBF];
#pragma unroll
        for (int v = 0; v < 5; v++) *(float4*)&p[v * 4] = pp4[v];
        float fc = g_fcut[e];
        float Wq = fc * FBq, Wr = fc * FBr, Wm = fc * FBm;
#pragma unroll
        for (int r = 0; r < NRBF; r++) {
            Wq = fmaf(p[r], WQc[r], Wq);
            Wr = fmaf(p[r], WRc[r], Wr);
            Wm = fmaf(p[r], WMc[r], Wm);
        }
        const float* xr = &x[(size_t)j * 384];
        float xq = xr[c], xR = xr[128 + c], xM = xr[256 + c];
        float d0 = g_dir[e * 3 + 0], d1 = g_dir[e * 3 + 1], d2 = g_dir[e * 3 + 2];
        accq = fmaf(Wq, xq, accq);
        float t   = Wr * xR;
        float wmx = Wm * xM;
        const float* mj = &mu_in[(size_t)j * 384];
        am0 = fmaf(t, d0, fmaf(wmx, mj[c],       am0));
        am1 = fmaf(t, d1, fmaf(wmx, mj[128 + c], am1));
        am2 = fmaf(t, d2, fmaf(wmx, mj[256 + c], am2));
    }
    q[(size_t)node * 128 + c] += accq;
    size_t mb = (size_t)node * 384;
    mu_out[mb + c]       = mu_in[mb + c]       + am0;
    mu_out[mb + 128 + c] = mu_in[mb + 128 + c] + am1;
    mu_out[mb + 256 + c] = mu_in[mb + 256 + c] + am2;
}

// ---------------- mixing stage 1: norms, dot, build ctx ----------------
__global__ void mix1_kernel(const float* __restrict__ q, int N) {
    int t = blockIdx.x * blockDim.x + threadIdx.x;
    if (t >= N * 128) return;
    int n = t >> 7, c = t & 127;
    const float* mm = &g_mumix[(size_t)n * 768];
    float v0 = mm[c],        v1 = mm[256 + c], v2 = mm[512 + c];
    float w0 = mm[128 + c],  w1 = mm[384 + c], w2 = mm[640 + c];
    float vn = sqrtf(v0 * v0 + v1 * v1 + v2 * v2 + 1e-8f);
    g_ctx[(size_t)n * 256 + c]       = q[t];
    g_ctx[(size_t)n * 256 + 128 + c] = vn;
    g_s[t] = v0 * w0 + v1 * w1 + v2 * w2;
}

// ---------------- mixing stage 2: final per-node update ----------------
__global__ void epi2_kernel(float* __restrict__ q, float* __restrict__ mu, int N) {
    int t = blockIdx.x * blockDim.x + threadIdx.x;
    if (t >= N * 128) return;
    int n = t >> 7, c = t & 127;
    const float* xr = &g_x[(size_t)n * 384];
    float dq   = xr[c];
    float dmu  = xr[128 + c];
    float dqmu = xr[256 + c];
    q[t] += dq + dqmu * g_s[t];
    const float* mm = &g_mumix[(size_t)n * 768];
    size_t mb = (size_t)n * 384;
    mu[mb + c]       += dmu * mm[128 + c];
    mu[mb + 128 + c] += dmu * mm[384 + c];
    mu[mb + 256 + c] += dmu * mm[640 + c];
}

// ---------------- host launch ----------------
extern "C" void kernel_launch(void* const* d_in, const int* in_sizes, int n_in,
                              void* d_out, int out_size) {
    const int*   an     = (const int*)  d_in[0];
    const float* r_ij   = (const float*)d_in[1];
    const int*   idx_i  = (const int*)  d_in[2];
    const int*   idx_j  = (const int*)  d_in[3];
    const float* emb    = (const float*)d_in[4];
    const float* filt_W = (const float*)d_in[5];
    const float* filt_b = (const float*)d_in[6];
    const float* int_W1 = (const float*)d_in[7];
    const float* int_b1 = (const float*)d_in[8];
    const float* int_W2 = (const float*)d_in[9];
    const float* int_b2 = (const float*)d_in[10];
    const float* mix_W1 = (const float*)d_in[11];
    const float* mix_b1 = (const float*)d_in[12];
    const float* mix_W2 = (const float*)d_in[13];
    const float* mix_b2 = (const float*)d_in[14];
    const float* mux_W  = (const float*)d_in[15];

    int N = in_sizes[0];
    int E = in_sizes[3];

    float* q      = (float*)d_out;          // [N,128]
    float* mu_out = q + (size_t)N * 128;    // [N,3,128]

    void* pA; cudaGetSymbolAddress(&pA, g_muA);  float* muA  = (float*)pA;
    void* pH; cudaGetSymbolAddress(&pH, g_h);    float* h    = (float*)pH;
    void* pX; cudaGetSymbolAddress(&pX, g_x);    float* xbuf = (float*)pX;
    void* pM; cudaGetSymbolAddress(&pM, g_mumix);float* mumix= (float*)pM;
    void* pC; cudaGetSymbolAddress(&pC, g_ctx);  float* ctx  = (float*)pC;

    // precompute
    pre_kernel   <<<(E + 255) / 256, 256>>>(r_ij, E);
    rowptr_kernel<<<(N + 256) / 256, 256>>>(idx_i, E, N);
    init_kernel  <<<((size_t)N * 384 + 255) / 256, 256>>>(an, emb, q, N);

    for (int l = 0; l < NLAYERS; l++) {
        float* mu_in = (l & 1) ? mu_out : muA;
        float* mu_o  = (l & 1) ? muA    : mu_out;

        // interaction: h = silu(q W1 + b1); x = h W2 + b2
        {
            dim3 g(128 / 64, (N + 63) / 64);
            gemm64<1><<<g, 256>>>(q, int_W1 + (size_t)l * 128 * 128,
                                  int_b1 + l * 128, h, N, 128, 128);
        }
        {
            dim3 g(384 / 64, (N + 63) / 64);
            gemm64<0><<<g, 256>>>(h, int_W2 + (size_t)l * 128 * 384,
                                  int_b2 + l * 384, xbuf, N, 384, 128);
        }
        // edge messages + segment sum (one block per node)
        edge_kernel<<<N, 128>>>(xbuf, q, mu_in, mu_o, idx_j,
                                filt_W, filt_b, l, N);
        // mixing: mumix = mu @ mux_W (no bias), A viewed as [3N,128]
        {
            dim3 g(256 / 64, (3 * N + 63) / 64);
            gemm64<0><<<g, 256>>>(mu_o, mux_W + (size_t)l * 128 * 256,
                                  nullptr, mumix, 3 * N, 256, 128);
        }
        mix1_kernel<<<((size_t)N * 128 + 255) / 256, 256>>>(q, N);
        // h = silu(ctx mix_W1 + b1)
        {
            dim3 g(128 / 64, (N + 63) / 64);
            gemm64<1><<<g, 256>>>(ctx, mix_W1 + (size_t)l * 256 * 128,
                                  mix_b1 + l * 128, h, N, 128, 256);
        }
        // x2 = h mix_W2 + b2 (into xbuf)
        {
            dim3 g(384 / 64, (N + 63) / 64);
            gemm64<0><<<g, 256>>>(h, mix_W2 + (size_t)l * 128 * 384,
                                  mix_b2 + l * 384, xbuf, N, 384, 128);
        }
        epi2_kernel<<<((size_t)N * 128 + 255) / 256, 256>>>(q, mu_o, N);
    }
    // layer parity: l=0 in=muA out=d_out, l=1 in=d_out out=muA, l=2 in=muA out=d_out.
    // Final q and mu land in d_out. (q lives in d_out throughout.)
}